// round 5
// baseline (speedup 1.0000x reference)
#include <cuda_runtime.h>

// Window_89696097010079 : Graves attention window
//   B=256, T=2048, V=128, C=512, K=10
// Inputs (metadata order): x(B,C) f32, kappa_old(B,K) f32, onehots(B,T,V) f32,
//                          W(3K,C) f32, b(3K) f32
// Output: concat of w(B,V), kappa(B,K), phi(B,T)  -> 559616 f32
//
// Strategy: one block per batch row, fully fused.
//   Phase 1: params = exp(x @ W^T + b)  (30 dots of len 512; 16 threads/output)
//   Phase 2: kappa = kappa_old + pre_kappa
//   Phase 3: phi[t] = sum_k alpha_k * exp(-beta_k*(kappa_k - t)^2)  -> smem + out
//   Phase 4: w[v] = sum_t phi[t] * onehots[b,t,v]   (HBM-bound, 268 MB total)
//            warp lanes cover v as float4 (512B coalesced row), 16 warps stripe t,
//            software-pipelined streaming loads (__ldcs) for high MLP + no cache
//            pollution (onehots is touched exactly once).

#define Bn 256
#define Tn 2048
#define Vn 128
#define Cn 512
#define Kn 10

__global__ __launch_bounds__(512)
void window_fused_kernel(const float* __restrict__ x,
                         const float* __restrict__ kappa_old,
                         const float* __restrict__ onehots,
                         const float* __restrict__ W,
                         const float* __restrict__ bias,
                         float* __restrict__ out)
{
    __shared__ float  s_x[Cn];
    __shared__ float  s_params[32];   // [0:10)=alpha, [10:20)=beta, [20:30)=kappa
    __shared__ float  s_phi[Tn];
    __shared__ float4 s_red[16][32];

    const int b   = blockIdx.x;
    const int tid = threadIdx.x;

    // ---- load x row ----
    s_x[tid] = x[(size_t)b * Cn + tid];
    __syncthreads();

    // ---- Phase 1+2: params = exp(x@W^T + b); kappa = kappa_old + pre_kappa ----
    if (tid < 480) {
        const int j   = tid >> 4;    // output index 0..29
        const int sub = tid & 15;    // 16 threads per output
        const float* wrow = W + j * Cn + sub * 32;
        const float* xs   = s_x + sub * 32;
        float p0 = 0.f, p1 = 0.f, p2 = 0.f, p3 = 0.f;
        #pragma unroll
        for (int i = 0; i < 32; i += 4) {
            p0 = fmaf(xs[i + 0], wrow[i + 0], p0);
            p1 = fmaf(xs[i + 1], wrow[i + 1], p1);
            p2 = fmaf(xs[i + 2], wrow[i + 2], p2);
            p3 = fmaf(xs[i + 3], wrow[i + 3], p3);
        }
        float p = (p0 + p1) + (p2 + p3);
        p += __shfl_down_sync(0xffffffffu, p, 8, 16);
        p += __shfl_down_sync(0xffffffffu, p, 4, 16);
        p += __shfl_down_sync(0xffffffffu, p, 2, 16);
        p += __shfl_down_sync(0xffffffffu, p, 1, 16);
        if (sub == 0) {
            float v = expf(p + bias[j]);
            if (j >= 20) {
                v += kappa_old[b * Kn + (j - 20)];
                out[Bn * Vn + b * Kn + (j - 20)] = v;   // kappa output
            }
            s_params[j] = v;
        }
    }
    __syncthreads();

    // ---- Phase 3: phi ----
    float* out_phi = out + (size_t)Bn * Vn + Bn * Kn + (size_t)b * Tn;
    for (int t = tid; t < Tn; t += 512) {
        const float tf = (float)t;
        float acc = 0.f;
        #pragma unroll
        for (int k = 0; k < Kn; k++) {
            const float d = s_params[20 + k] - tf;
            acc = fmaf(s_params[k], expf(-s_params[10 + k] * d * d), acc);
        }
        s_phi[t] = acc;
        out_phi[t] = acc;
    }
    __syncthreads();

    // ---- Phase 4: w[v] = sum_t phi[t] * onehots[b,t,v]  (268 MB streaming read) ----
    const int v4 = tid & 31;    // lane -> float4 column group
    const int ts = tid >> 5;    // warp -> t stripe 0..15
    const float4* oh = reinterpret_cast<const float4*>(
        onehots + (size_t)b * Tn * Vn + v4 * 4);
    float4 acc0 = make_float4(0.f, 0.f, 0.f, 0.f);
    float4 acc1 = make_float4(0.f, 0.f, 0.f, 0.f);

    // 2048 / 16 = 128 iters per thread; 4 per loop, loads front-batched.
    // Row stride in float4 units: Vn/4 = 32.
    #pragma unroll 1
    for (int t = ts; t < Tn; t += 64) {
        const float4 o0 = __ldcs(oh + (size_t)(t)      * (Vn / 4));
        const float4 o1 = __ldcs(oh + (size_t)(t + 16) * (Vn / 4));
        const float4 o2 = __ldcs(oh + (size_t)(t + 32) * (Vn / 4));
        const float4 o3 = __ldcs(oh + (size_t)(t + 48) * (Vn / 4));
        const float p0 = s_phi[t];
        const float p1 = s_phi[t + 16];
        const float p2 = s_phi[t + 32];
        const float p3 = s_phi[t + 48];
        acc0.x = fmaf(p0, o0.x, acc0.x); acc0.y = fmaf(p0, o0.y, acc0.y);
        acc0.z = fmaf(p0, o0.z, acc0.z); acc0.w = fmaf(p0, o0.w, acc0.w);
        acc1.x = fmaf(p1, o1.x, acc1.x); acc1.y = fmaf(p1, o1.y, acc1.y);
        acc1.z = fmaf(p1, o1.z, acc1.z); acc1.w = fmaf(p1, o1.w, acc1.w);
        acc0.x = fmaf(p2, o2.x, acc0.x); acc0.y = fmaf(p2, o2.y, acc0.y);
        acc0.z = fmaf(p2, o2.z, acc0.z); acc0.w = fmaf(p2, o2.w, acc0.w);
        acc1.x = fmaf(p3, o3.x, acc1.x); acc1.y = fmaf(p3, o3.y, acc1.y);
        acc1.z = fmaf(p3, o3.z, acc1.z); acc1.w = fmaf(p3, o3.w, acc1.w);
    }
    acc0.x += acc1.x; acc0.y += acc1.y; acc0.z += acc1.z; acc0.w += acc1.w;
    s_red[ts][v4] = acc0;
    __syncthreads();

    if (tid < 32) {
        float4 r = s_red[0][tid];
        #pragma unroll
        for (int i = 1; i < 16; i++) {
            const float4 q = s_red[i][tid];
            r.x += q.x; r.y += q.y; r.z += q.z; r.w += q.w;
        }
        reinterpret_cast<float4*>(out + (size_t)b * Vn)[tid] = r;   // w output
    }
}

extern "C" void kernel_launch(void* const* d_in, const int* in_sizes, int n_in,
                              void* d_out, int out_size)
{
    (void)in_sizes; (void)n_in; (void)out_size;
    const float* x         = (const float*)d_in[0];
    const float* kappa_old = (const float*)d_in[1];
    const float* onehots   = (const float*)d_in[2];
    const float* W         = (const float*)d_in[3];
    const float* bias      = (const float*)d_in[4];
    float* out = (float*)d_out;
    window_fused_kernel<<<Bn, 512>>>(x, kappa_old, onehots, W, bias, out);
}